// round 4
// baseline (speedup 1.0000x reference)
#include <cuda_runtime.h>
#include <cuda_bf16.h>
#include <cstdint>

#define DIM 256
#define NBINS 32
#define CT 32            // columns per tile
#define MINW 1e-3f
#define MINH 1e-3f
#define MIND 1e-3f

// Precomputed per-(dim,bin) tables
__device__ float4 g_pA[DIM * NBINS];   // {cw_lo, 1/w, ch_lo, h}
__device__ float2 g_pB[DIM * NBINS];   // {d0, d1}

__device__ __forceinline__ float softplus_min(float v) {
    float sp = (v > 15.f) ? v : log1pf(expf(v));
    return MIND + sp;
}

// One warp per dim: softmax -> floor -> cumsum for widths & heights, derivatives.
__global__ void spline_precompute_kernel(const float* __restrict__ width,
                                         const float* __restrict__ height,
                                         const float* __restrict__ deriv) {
    int d = blockIdx.x;
    int t = threadIdx.x;   // 0..31

    // ---- widths ----
    float wv = width[d * NBINS + t];
    float m = wv;
    #pragma unroll
    for (int o = 16; o; o >>= 1) m = fmaxf(m, __shfl_xor_sync(0xFFFFFFFFu, m, o));
    float e = __expf(wv - m);
    float s = e;
    #pragma unroll
    for (int o = 16; o; o >>= 1) s += __shfl_xor_sync(0xFFFFFFFFu, s, o);
    float sz = MINW + (1.f - NBINS * MINW) * (e / s);
    float incl = sz;
    #pragma unroll
    for (int o = 1; o < 32; o <<= 1) {
        float v = __shfl_up_sync(0xFFFFFFFFu, incl, o);
        if (t >= o) incl += v;
    }
    float cw_hi = (t == 31) ? 1.f : incl;
    float up = __shfl_up_sync(0xFFFFFFFFu, incl, 1);
    float cw_lo = (t == 0) ? 0.f : up;
    float w = cw_hi - cw_lo;

    // ---- heights ----
    float hv = height[d * NBINS + t];
    float mh = hv;
    #pragma unroll
    for (int o = 16; o; o >>= 1) mh = fmaxf(mh, __shfl_xor_sync(0xFFFFFFFFu, mh, o));
    float eh = __expf(hv - mh);
    float sh = eh;
    #pragma unroll
    for (int o = 16; o; o >>= 1) sh += __shfl_xor_sync(0xFFFFFFFFu, sh, o);
    float szh = MINH + (1.f - NBINS * MINH) * (eh / sh);
    float inclh = szh;
    #pragma unroll
    for (int o = 1; o < 32; o <<= 1) {
        float v = __shfl_up_sync(0xFFFFFFFFu, inclh, o);
        if (t >= o) inclh += v;
    }
    float ch_hi = (t == 31) ? 1.f : inclh;
    float uph = __shfl_up_sync(0xFFFFFFFFu, inclh, 1);
    float ch_lo = (t == 0) ? 0.f : uph;
    float h = ch_hi - ch_lo;

    // ---- derivatives (boundary == 1 exactly) ----
    float d0 = (t == 0)  ? 1.f : softplus_min(deriv[d * (NBINS - 1) + t - 1]);
    float d1 = (t == 31) ? 1.f : softplus_min(deriv[d * (NBINS - 1) + t]);

    float invw = 1.f / w;

    g_pA[d * NBINS + t] = make_float4(cw_lo, invw, ch_lo, h);
    g_pB[d * NBINS + t] = make_float2(d0, d1);
}

__device__ __forceinline__ void spline_eval(const float4* __restrict__ colA,
                                            const float2* __restrict__ colB,
                                            float xs, float& yo, float& lo) {
    float xc = fminf(fmaxf(xs, 0.f), 1.f);

    // uniform guess + retry using cw_lo/invw from the gathered params
    int b = __float2int_rd(xc * 32.f);
    b = (b > 31) ? 31 : b;
    float4 pa = colA[b];
    float theta = (xc - pa.x) * pa.y;
    while (theta < 0.f && b > 0) {
        --b; pa = colA[b]; theta = (xc - pa.x) * pa.y;
    }
    while (theta >= 1.f && b < NBINS - 1) {
        ++b; pa = colA[b]; theta = (xc - pa.x) * pa.y;
    }

    const float2 pb = colB[b];

    float omt    = 1.f - theta;
    float t1m    = theta * omt;
    float th2    = theta * theta;
    float h      = pa.w;
    float delta  = h * pa.y;        // h * invw
    float delta2 = delta * delta;
    float dd0 = pb.x, dd1 = pb.y;

    float num  = h * fmaf(delta, th2, dd0 * t1m);
    float den  = fmaf(dd0 + dd1 - 2.f * delta, t1m, delta);
    float rden = __fdividef(1.f, den);
    float yin  = fmaf(num, rden, pa.z);

    float dnum = delta2 * fmaf(dd1, th2, fmaf(2.f * delta, t1m, dd0 * omt * omt));
    float lin  = __logf(dnum * rden * rden);

    bool inside = (xs >= 0.f) && (xs <= 1.f);
    yo = inside ? yin : xs;
    lo = inside ? lin : 0.f;
}

// Main kernel: each block owns a 32-column tile; tables live in smem.
// Each thread processes 2 rows (base+rown, base+rown+32) x 4 columns.
__global__ void __launch_bounds__(256)
spline_main_kernel(const float* __restrict__ x, float* __restrict__ out, int B) {
    __shared__ float4 s_pA[CT * NBINS];   // 16 KB
    __shared__ float2 s_pB[CT * NBINS];   //  8 KB

    const int colBase = blockIdx.y * CT;
    const int tid = threadIdx.x;

    for (int i = tid; i < CT * NBINS; i += 256) {
        s_pA[i] = g_pA[colBase * NBINS + i];
        s_pB[i] = g_pB[colBase * NBINS + i];
    }
    __syncthreads();

    const int cg   = tid & 7;     // colgroup 0..7 (4 cols each)
    const int rown = tid >> 3;    // 0..31
    const int lc0  = cg * 4;
    const int colOff = colBase + lc0;

    float* __restrict__ outY = out;
    float* __restrict__ outL = out + (size_t)B * DIM;

    // B is a multiple of 64; each block consumes 64 rows per iteration.
    for (int base = blockIdx.x * 64; base < B; base += gridDim.x * 64) {
        const int r0 = base + rown;
        const int r1 = r0 + 32;
        const float4 xv0 = *(const float4*)(x + (size_t)r0 * DIM + colOff);
        const float4 xv1 = *(const float4*)(x + (size_t)r1 * DIM + colOff);

        float y0[4], l0[4], y1[4], l1[4];
        #pragma unroll
        for (int k = 0; k < 4; k++) {
            const float4* colA = s_pA + (lc0 + k) * NBINS;
            const float2* colB = s_pB + (lc0 + k) * NBINS;
            float xs0 = (k == 0) ? xv0.x : (k == 1) ? xv0.y : (k == 2) ? xv0.z : xv0.w;
            float xs1 = (k == 0) ? xv1.x : (k == 1) ? xv1.y : (k == 2) ? xv1.z : xv1.w;
            spline_eval(colA, colB, xs0, y0[k], l0[k]);
            spline_eval(colA, colB, xs1, y1[k], l1[k]);
        }
        *(float4*)(outY + (size_t)r0 * DIM + colOff) = make_float4(y0[0], y0[1], y0[2], y0[3]);
        *(float4*)(outY + (size_t)r1 * DIM + colOff) = make_float4(y1[0], y1[1], y1[2], y1[3]);
        *(float4*)(outL + (size_t)r0 * DIM + colOff) = make_float4(l0[0], l0[1], l0[2], l0[3]);
        *(float4*)(outL + (size_t)r1 * DIM + colOff) = make_float4(l1[0], l1[1], l1[2], l1[3]);
    }
}

extern "C" void kernel_launch(void* const* d_in, const int* in_sizes, int n_in,
                              void* d_out, int out_size) {
    const float* x      = (const float*)d_in[0];
    const float* width  = (const float*)d_in[1];
    const float* height = (const float*)d_in[2];
    const float* deriv  = (const float*)d_in[3];
    float* out = (float*)d_out;

    const int B = in_sizes[0] / DIM;

    spline_precompute_kernel<<<DIM, 32>>>(width, height, deriv);

    dim3 grid(148, DIM / CT);   // 1184 blocks = 148 SMs x 8 blocks (full thread wave)
    spline_main_kernel<<<grid, 256>>>(x, out, B);
}

// round 6
// speedup vs baseline: 1.1305x; 1.1305x over previous
#include <cuda_runtime.h>
#include <cuda_bf16.h>
#include <cstdint>

#define DIM 256
#define NBINS 32
#define CT 32            // columns per tile
#define MINW 1e-3f
#define MINH 1e-3f
#define MIND 1e-3f

// Precomputed per-(dim,bin) tables
__device__ float4 g_pA[DIM * NBINS];   // {cw_lo, 1/w, ch_lo, h}
__device__ float2 g_pB[DIM * NBINS];   // {d0, d1}

__device__ __forceinline__ float softplus_min(float v) {
    float sp = (v > 15.f) ? v : log1pf(expf(v));
    return MIND + sp;
}

// One warp per dim: softmax -> floor -> cumsum for widths & heights, derivatives.
__global__ void spline_precompute_kernel(const float* __restrict__ width,
                                         const float* __restrict__ height,
                                         const float* __restrict__ deriv) {
    int d = blockIdx.x;
    int t = threadIdx.x;   // 0..31

    // ---- widths ----
    float wv = width[d * NBINS + t];
    float m = wv;
    #pragma unroll
    for (int o = 16; o; o >>= 1) m = fmaxf(m, __shfl_xor_sync(0xFFFFFFFFu, m, o));
    float e = __expf(wv - m);
    float s = e;
    #pragma unroll
    for (int o = 16; o; o >>= 1) s += __shfl_xor_sync(0xFFFFFFFFu, s, o);
    float sz = MINW + (1.f - NBINS * MINW) * (e / s);
    float incl = sz;
    #pragma unroll
    for (int o = 1; o < 32; o <<= 1) {
        float v = __shfl_up_sync(0xFFFFFFFFu, incl, o);
        if (t >= o) incl += v;
    }
    float cw_hi = (t == 31) ? 1.f : incl;
    float up = __shfl_up_sync(0xFFFFFFFFu, incl, 1);
    float cw_lo = (t == 0) ? 0.f : up;
    float w = cw_hi - cw_lo;

    // ---- heights ----
    float hv = height[d * NBINS + t];
    float mh = hv;
    #pragma unroll
    for (int o = 16; o; o >>= 1) mh = fmaxf(mh, __shfl_xor_sync(0xFFFFFFFFu, mh, o));
    float eh = __expf(hv - mh);
    float sh = eh;
    #pragma unroll
    for (int o = 16; o; o >>= 1) sh += __shfl_xor_sync(0xFFFFFFFFu, sh, o);
    float szh = MINH + (1.f - NBINS * MINH) * (eh / sh);
    float inclh = szh;
    #pragma unroll
    for (int o = 1; o < 32; o <<= 1) {
        float v = __shfl_up_sync(0xFFFFFFFFu, inclh, o);
        if (t >= o) inclh += v;
    }
    float ch_hi = (t == 31) ? 1.f : inclh;
    float uph = __shfl_up_sync(0xFFFFFFFFu, inclh, 1);
    float ch_lo = (t == 0) ? 0.f : uph;
    float h = ch_hi - ch_lo;

    // ---- derivatives (boundary == 1 exactly) ----
    float d0 = (t == 0)  ? 1.f : softplus_min(deriv[d * (NBINS - 1) + t - 1]);
    float d1 = (t == 31) ? 1.f : softplus_min(deriv[d * (NBINS - 1) + t]);

    float invw = 1.f / w;

    g_pA[d * NBINS + t] = make_float4(cw_lo, invw, ch_lo, h);
    g_pB[d * NBINS + t] = make_float2(d0, d1);
}

// Main kernel: each block owns a 32-column tile; tables live in smem.
// Bin lookup = uniform guess + gather-retry (no binary search).
__global__ void __launch_bounds__(256, 8)
spline_main_kernel(const float* __restrict__ x, float* __restrict__ out, int B) {
    __shared__ float4 s_pA[CT * NBINS];   // 16 KB
    __shared__ float2 s_pB[CT * NBINS];   //  8 KB

    const int colBase = blockIdx.y * CT;
    const int tid = threadIdx.x;

    for (int i = tid; i < CT * NBINS; i += 256) {
        s_pA[i] = g_pA[colBase * NBINS + i];
        s_pB[i] = g_pB[colBase * NBINS + i];
    }
    __syncthreads();

    const int cg   = tid & 7;     // colgroup 0..7 (4 cols each)
    const int rown = tid >> 3;    // 0..31
    const int lc0  = cg * 4;
    const int colOff = colBase + lc0;

    float* __restrict__ outY = out;
    float* __restrict__ outL = out + (size_t)B * DIM;

    for (int row = blockIdx.x * 32 + rown; row < B; row += gridDim.x * 32) {
        const float4 xv = *(const float4*)(x + (size_t)row * DIM + colOff);
        float yv[4], lv[4];
        #pragma unroll
        for (int k = 0; k < 4; k++) {
            const int lc = lc0 + k;
            const float4* __restrict__ colA = s_pA + lc * NBINS;
            float xs = (k == 0) ? xv.x : (k == 1) ? xv.y : (k == 2) ? xv.z : xv.w;
            float xc = fminf(fmaxf(xs, 0.f), 1.f);

            // uniform guess + retry using cw_lo/invw from the gathered params
            int b = __float2int_rd(xc * 32.f);
            b = (b > 31) ? 31 : b;
            float4 pa = colA[b];
            float theta = (xc - pa.x) * pa.y;
            while (theta < 0.f && b > 0) {
                --b; pa = colA[b]; theta = (xc - pa.x) * pa.y;
            }
            while (theta >= 1.f && b < NBINS - 1) {
                ++b; pa = colA[b]; theta = (xc - pa.x) * pa.y;
            }

            const float2 pb = s_pB[lc * NBINS + b];

            float omt    = 1.f - theta;
            float t1m    = theta * omt;
            float th2    = theta * theta;
            float h      = pa.w;
            float delta  = h * pa.y;        // h * invw
            float delta2 = delta * delta;
            float dd0 = pb.x, dd1 = pb.y;

            float num  = h * fmaf(delta, th2, dd0 * t1m);
            float den  = fmaf(dd0 + dd1 - 2.f * delta, t1m, delta);
            float rden = __fdividef(1.f, den);
            float yin  = fmaf(num, rden, pa.z);

            float dnum = delta2 * fmaf(dd1, th2, fmaf(2.f * delta, t1m, dd0 * omt * omt));
            float lin  = __logf(dnum * rden * rden);

            bool inside = (xs >= 0.f) && (xs <= 1.f);
            yv[k] = inside ? yin : xs;
            lv[k] = inside ? lin : 0.f;
        }
        *(float4*)(outY + (size_t)row * DIM + colOff) = make_float4(yv[0], yv[1], yv[2], yv[3]);
        *(float4*)(outL + (size_t)row * DIM + colOff) = make_float4(lv[0], lv[1], lv[2], lv[3]);
    }
}

extern "C" void kernel_launch(void* const* d_in, const int* in_sizes, int n_in,
                              void* d_out, int out_size) {
    const float* x      = (const float*)d_in[0];
    const float* width  = (const float*)d_in[1];
    const float* height = (const float*)d_in[2];
    const float* deriv  = (const float*)d_in[3];
    float* out = (float*)d_out;

    const int B = in_sizes[0] / DIM;

    spline_precompute_kernel<<<DIM, 32>>>(width, height, deriv);

    dim3 grid(148, DIM / CT);   // 1184 blocks = 148 SMs x 8 blocks x 256 thr = full thread wave
    spline_main_kernel<<<grid, 256>>>(x, out, B);
}